// round 4
// baseline (speedup 1.0000x reference)
#include <cuda_runtime.h>
#include <cstdint>
#include <cstddef>

#define N_NODES 50000
#define N_EDGES 800000

// Scratch (device globals: no allocation allowed)
__device__ __align__(16) float g_xw1[N_NODES * 64];   // x@W1[:64]+b1, later agg_mean@W2 result
__device__ __align__(16) float g_agg[N_NODES * 64];   // scatter-add of relu(h)
__device__ float g_cnt[N_NODES];                      // in-degree counts

typedef unsigned long long u64;

__device__ __forceinline__ u64 pack2(float v) {
    u64 r; asm("mov.b64 %0, {%1, %1};" : "=l"(r) : "f"(v)); return r;
}
__device__ __forceinline__ void unpack2(u64 v, float &lo, float &hi) {
    asm("mov.b64 {%0, %1}, %2;" : "=f"(lo), "=f"(hi) : "l"(v));
}
__device__ __forceinline__ void ffma2(u64 &d, u64 a, u64 b) {
    asm("fma.rn.f32x2 %0, %1, %2, %0;" : "+l"(d) : "l"(a), "l"(b));
}
__device__ __forceinline__ void red_add_v4(float* addr, float4 v) {
    asm volatile("red.global.add.v4.f32 [%0], {%1, %2, %3, %4};"
                 :: "l"(addr), "f"(v.x), "f"(v.y), "f"(v.z), "f"(v.w)
                 : "memory");
}

// All kernels: 256 threads = 8 warps; warp pair (2w, 2w+1) covers the same 32
// items, warp parity h = which half of the 64 outputs this thread produces.
// h is warp-uniform so shared-weight reads stay single-phase broadcasts.

// ---------------------------------------------------------------------------
// Precompute: g_xw1[n][h*32..] = x[n] @ W1[0:64, h*32..] + b1[h*32..]
// Also zeroes g_agg half-row and (h==0) g_cnt.
// ---------------------------------------------------------------------------
__global__ void __launch_bounds__(256) precompute_kernel(
        const float* __restrict__ x,
        const float* __restrict__ W1,
        const float* __restrict__ b1) {
    __shared__ ulonglong2 sW[64 * 16];   // full W1[0:64], 16 KB
    __shared__ ulonglong2 sb[16];
    int tid = threadIdx.x;
    const ulonglong2* W1v = reinterpret_cast<const ulonglong2*>(W1);
    for (int idx = tid; idx < 64 * 16; idx += 256) sW[idx] = W1v[idx];
    if (tid < 16) sb[tid] = reinterpret_cast<const ulonglong2*>(b1)[tid];
    __syncthreads();

    int warp = tid >> 5, lane = tid & 31;
    int h = warp & 1, g = warp >> 1;
    int n = blockIdx.x * 128 + g * 32 + lane;
    if (n >= N_NODES) return;

    u64 acc[16];
    #pragma unroll
    for (int j = 0; j < 8; j++) { ulonglong2 v = sb[h * 8 + j]; acc[2*j] = v.x; acc[2*j+1] = v.y; }

    const float4* xr = reinterpret_cast<const float4*>(x + (size_t)n * 64);
    #pragma unroll 1
    for (int c = 0; c < 2; c++) {
        float v[32];
        #pragma unroll
        for (int j = 0; j < 8; j++) {
            float4 f = xr[c * 8 + j];
            v[4*j] = f.x; v[4*j+1] = f.y; v[4*j+2] = f.z; v[4*j+3] = f.w;
        }
        #pragma unroll
        for (int i = 0; i < 32; i++) {
            u64 a = pack2(v[i]);
            #pragma unroll
            for (int j = 0; j < 8; j++) {
                ulonglong2 w = sW[(c * 32 + i) * 16 + h * 8 + j];
                ffma2(acc[2*j], a, w.x);
                ffma2(acc[2*j+1], a, w.y);
            }
        }
    }
    ulonglong2* o = reinterpret_cast<ulonglong2*>(g_xw1 + (size_t)n * 64 + h * 32);
    float4* az = reinterpret_cast<float4*>(g_agg + (size_t)n * 64 + h * 32);
    float4 z = make_float4(0.f, 0.f, 0.f, 0.f);
    #pragma unroll
    for (int j = 0; j < 8; j++) {
        ulonglong2 v; v.x = acc[2*j]; v.y = acc[2*j+1]; o[j] = v;
        az[j] = z;
    }
    if (h == 0) g_cnt[n] = 0.0f;
}

// ---------------------------------------------------------------------------
// Edge kernel: 2 threads per edge (half outputs each).
//   h = xw1[src][half] + ef @ W1[64:80, half] ; scatter relu(h); (h==0) cnt++
// ---------------------------------------------------------------------------
__global__ void __launch_bounds__(256) edge_kernel(
        const int*   __restrict__ ei,
        const float* __restrict__ ef,
        const float* __restrict__ W1) {
    __shared__ ulonglong2 sW1e[16 * 16];  // W1 rows 64..79, 4 KB
    int tid = threadIdx.x;
    const ulonglong2* W1v = reinterpret_cast<const ulonglong2*>(W1);
    for (int idx = tid; idx < 16 * 16; idx += 256) sW1e[idx] = W1v[1024 + idx];
    __syncthreads();

    int warp = tid >> 5, lane = tid & 31;
    int hh = warp & 1, g = warp >> 1;
    int e = blockIdx.x * 128 + g * 32 + lane;   // N_EDGES % 128 == 0
    int s = ei[e];
    int d = ei[N_EDGES + e];

    // acc <- xw1[src] half (L2-resident gather, 128 B)
    u64 acc[16];
    const ulonglong2* xr = reinterpret_cast<const ulonglong2*>(g_xw1 + (size_t)s * 64 + hh * 32);
    #pragma unroll
    for (int j = 0; j < 8; j++) { ulonglong2 v = xr[j]; acc[2*j] = v.x; acc[2*j+1] = v.y; }

    float efr[16];
    const float4* er = reinterpret_cast<const float4*>(ef + (size_t)e * 16);
    #pragma unroll
    for (int j = 0; j < 4; j++) {
        float4 f = er[j];
        efr[4*j] = f.x; efr[4*j+1] = f.y; efr[4*j+2] = f.z; efr[4*j+3] = f.w;
    }

    // acc += ef @ W1e[:, half]
    #pragma unroll
    for (int i = 0; i < 16; i++) {
        u64 a = pack2(efr[i]);
        #pragma unroll
        for (int j = 0; j < 8; j++) {
            ulonglong2 w = sW1e[i * 16 + hh * 8 + j];
            ffma2(acc[2*j], a, w.x);
            ffma2(acc[2*j+1], a, w.y);
        }
    }

    // relu + scatter half-row
    float* aggbase = g_agg + (size_t)d * 64 + hh * 32;
    #pragma unroll
    for (int j = 0; j < 8; j++) {
        float4 v;
        unpack2(acc[2*j],   v.x, v.y);
        unpack2(acc[2*j+1], v.z, v.w);
        v.x = fmaxf(v.x, 0.f); v.y = fmaxf(v.y, 0.f);
        v.z = fmaxf(v.z, 0.f); v.w = fmaxf(v.w, 0.f);
        red_add_v4(aggbase + 4 * j, v);
    }
    if (hh == 0) atomicAdd(&g_cnt[d], 1.0f);
}

// ---------------------------------------------------------------------------
// Node stage A: g_xw1[n][half] = (g_agg[n] @ W2[:, half]) * inv + b2[half]*(cnt*inv)
// ---------------------------------------------------------------------------
__global__ void __launch_bounds__(256) nodeA_kernel(
        const float* __restrict__ W2,
        const float* __restrict__ b2) {
    __shared__ ulonglong2 sW[64 * 16];   // 16 KB
    __shared__ float sb[64];
    int tid = threadIdx.x;
    const ulonglong2* W2v = reinterpret_cast<const ulonglong2*>(W2);
    for (int idx = tid; idx < 64 * 16; idx += 256) sW[idx] = W2v[idx];
    if (tid < 64) sb[tid] = b2[tid];
    __syncthreads();

    int warp = tid >> 5, lane = tid & 31;
    int h = warp & 1, g = warp >> 1;
    int n = blockIdx.x * 128 + g * 32 + lane;
    if (n >= N_NODES) return;

    float cnt = g_cnt[n];
    float inv = 1.0f / (cnt + 1e-8f);
    float bs  = cnt * inv;

    u64 acc[16];
    #pragma unroll
    for (int j = 0; j < 16; j++) acc[j] = 0ull;

    const float4* ar = reinterpret_cast<const float4*>(g_agg + (size_t)n * 64);
    #pragma unroll 1
    for (int c = 0; c < 2; c++) {
        float v[32];
        #pragma unroll
        for (int j = 0; j < 8; j++) {
            float4 f = ar[c * 8 + j];
            v[4*j] = f.x; v[4*j+1] = f.y; v[4*j+2] = f.z; v[4*j+3] = f.w;
        }
        #pragma unroll
        for (int i = 0; i < 32; i++) {
            u64 a = pack2(v[i]);
            #pragma unroll
            for (int j = 0; j < 8; j++) {
                ulonglong2 w = sW[(c * 32 + i) * 16 + h * 8 + j];
                ffma2(acc[2*j], a, w.x);
                ffma2(acc[2*j+1], a, w.y);
            }
        }
    }
    float4* o = reinterpret_cast<float4*>(g_xw1 + (size_t)n * 64 + h * 32);
    #pragma unroll
    for (int j = 0; j < 8; j++) {
        float4 v;
        unpack2(acc[2*j],   v.x, v.y);
        unpack2(acc[2*j+1], v.z, v.w);
        int b = h * 32 + 4 * j;
        v.x = v.x * inv + sb[b]   * bs;
        v.y = v.y * inv + sb[b+1] * bs;
        v.z = v.z * inv + sb[b+2] * bs;
        v.w = v.w * inv + sb[b+3] * bs;
        o[j] = v;
    }
}

// ---------------------------------------------------------------------------
// Node stage B: y = relu([x, agg_mean] @ W3 + b3) + x ; LayerNorm -> out
// Half-output threads; LN partials exchanged with tid^32 via smem.
// ---------------------------------------------------------------------------
__global__ void __launch_bounds__(256) nodeB_kernel(
        const float* __restrict__ x,
        const float* __restrict__ W3,
        const float* __restrict__ b3,
        const float* __restrict__ gamma,
        const float* __restrict__ beta,
        float* __restrict__ out) {
    __shared__ ulonglong2 sW[128 * 16];  // 32 KB
    __shared__ ulonglong2 sb[16];
    __shared__ float sg[64], sbt[64];
    __shared__ float2 sPart[256];
    int tid = threadIdx.x;
    const ulonglong2* W3v = reinterpret_cast<const ulonglong2*>(W3);
    for (int idx = tid; idx < 128 * 16; idx += 256) sW[idx] = W3v[idx];
    if (tid < 16) sb[tid] = reinterpret_cast<const ulonglong2*>(b3)[tid];
    if (tid < 64) { sg[tid] = gamma[tid]; sbt[tid] = beta[tid]; }
    __syncthreads();

    int warp = tid >> 5, lane = tid & 31;
    int h = warp & 1, g = warp >> 1;
    int n0 = blockIdx.x * 128 + g * 32 + lane;
    bool valid = (n0 < N_NODES);
    int n = valid ? n0 : (N_NODES - 1);   // clamp: no early return (sync below)

    u64 acc[16];
    #pragma unroll
    for (int j = 0; j < 8; j++) { ulonglong2 v = sb[h * 8 + j]; acc[2*j] = v.x; acc[2*j+1] = v.y; }

    const float4* xr = reinterpret_cast<const float4*>(x + (size_t)n * 64);
    const float4* ar = reinterpret_cast<const float4*>(g_xw1 + (size_t)n * 64);

    #pragma unroll 1
    for (int c = 0; c < 4; c++) {
        const float4* p = (c < 2) ? (xr + (c & 1) * 8) : (ar + (c & 1) * 8);
        float v[32];
        #pragma unroll
        for (int j = 0; j < 8; j++) {
            float4 f = p[j];
            v[4*j] = f.x; v[4*j+1] = f.y; v[4*j+2] = f.z; v[4*j+3] = f.w;
        }
        #pragma unroll
        for (int i = 0; i < 32; i++) {
            u64 a = pack2(v[i]);
            #pragma unroll
            for (int j = 0; j < 8; j++) {
                ulonglong2 w = sW[(c * 32 + i) * 16 + h * 8 + j];
                ffma2(acc[2*j], a, w.x);
                ffma2(acc[2*j+1], a, w.y);
            }
        }
    }

    // relu + residual (this half of x)
    float u[32];
    const float4* xh = reinterpret_cast<const float4*>(x + (size_t)n * 64 + h * 32);
    #pragma unroll
    for (int j = 0; j < 8; j++) {
        float4 f = xh[j];
        float a0, a1, a2, a3;
        unpack2(acc[2*j],   a0, a1);
        unpack2(acc[2*j+1], a2, a3);
        u[4*j]   = fmaxf(a0, 0.0f) + f.x;
        u[4*j+1] = fmaxf(a1, 0.0f) + f.y;
        u[4*j+2] = fmaxf(a2, 0.0f) + f.z;
        u[4*j+3] = fmaxf(a3, 0.0f) + f.w;
    }

    // LayerNorm partials over this half, exchange with partner (tid^32)
    float s = 0.0f, ss = 0.0f;
    #pragma unroll
    for (int j = 0; j < 32; j++) { s += u[j]; ss = fmaf(u[j], u[j], ss); }
    sPart[tid] = make_float2(s, ss);
    __syncthreads();
    float2 p2 = sPart[tid ^ 32];
    s += p2.x; ss += p2.y;

    float mu  = s * (1.0f / 64.0f);
    float var = ss * (1.0f / 64.0f) - mu * mu;
    float r   = rsqrtf(var + 1e-5f);

    if (valid) {
        float4* o = reinterpret_cast<float4*>(out + (size_t)n * 64 + h * 32);
        #pragma unroll
        for (int j = 0; j < 8; j++) {
            int b = h * 32 + 4 * j;
            float4 v;
            v.x = (u[4*j]   - mu) * r * sg[b]   + sbt[b];
            v.y = (u[4*j+1] - mu) * r * sg[b+1] + sbt[b+1];
            v.z = (u[4*j+2] - mu) * r * sg[b+2] + sbt[b+2];
            v.w = (u[4*j+3] - mu) * r * sg[b+3] + sbt[b+3];
            o[j] = v;
        }
    }
}

// ---------------------------------------------------------------------------
extern "C" void kernel_launch(void* const* d_in, const int* in_sizes, int n_in,
                              void* d_out, int out_size) {
    const float* x     = (const float*)d_in[0];
    const int*   ei    = (const int*)  d_in[1];
    const float* ef    = (const float*)d_in[2];
    const float* W1    = (const float*)d_in[3];
    const float* b1    = (const float*)d_in[4];
    const float* W2    = (const float*)d_in[5];
    const float* b2    = (const float*)d_in[6];
    const float* W3    = (const float*)d_in[7];
    const float* b3    = (const float*)d_in[8];
    const float* gamma = (const float*)d_in[9];
    const float* beta  = (const float*)d_in[10];
    float* out = (float*)d_out;

    (void)in_sizes; (void)n_in; (void)out_size;

    const int node_blocks = (N_NODES + 127) / 128;   // 128 nodes per 256-thread block
    precompute_kernel<<<node_blocks, 256>>>(x, W1, b1);
    edge_kernel<<<N_EDGES / 128, 256>>>(ei, ef, W1);
    nodeA_kernel<<<node_blocks, 256>>>(W2, b2);
    nodeB_kernel<<<node_blocks, 256>>>(x, W3, b3, gamma, beta, out);
}